// round 2
// baseline (speedup 1.0000x reference)
#include <cuda_runtime.h>
#include <math.h>

#define Nn 128
#define Hh 128
#define Ww 128

// ---------------- device scratch (allocation-free) ----------------
__device__ float g_h[Nn * 2 * Hh * Ww];      // conv1 output, 16.8 MB
__device__ float g_actT[8192 * Nn];          // pooled activation, transposed [k][n]
__device__ float g_a1T[2048 * Nn];           // fc1 output, transposed [o][n]
__device__ float g_a2T[1024 * Nn];           // fc2 output, transposed [o][n]

// ---------------- kernel 1: conv3x3 (9ch -> 2ch), pad 1 ----------------
__global__ __launch_bounds__(128) void conv1_kernel(
    const float* __restrict__ x, const float* __restrict__ mask,
    const float* __restrict__ w1, const float* __restrict__ b1)
{
    __shared__ float ws[162];
    __shared__ float bs[2];
    int tid = threadIdx.x;
    for (int t = tid; t < 162; t += 128) ws[t] = w1[t];
    if (tid < 2) bs[tid] = b1[tid];
    __syncthreads();

    int j = tid;
    int i = blockIdx.x;
    int n = blockIdx.y;

    float acc0 = bs[0], acc1 = bs[1];
    #pragma unroll
    for (int c = 0; c < 9; ++c) {
        const float* src = (c < 8) ? (x + ((size_t)(n * 8 + c)) * Hh * Ww)
                                   : (mask + (size_t)n * Hh * Ww);
        #pragma unroll
        for (int ky = 0; ky < 3; ++ky) {
            int yy = i + ky - 1;
            if (yy < 0 || yy >= Hh) continue;
            #pragma unroll
            for (int kx = 0; kx < 3; ++kx) {
                int xx = j + kx - 1;
                if (xx < 0 || xx >= Ww) continue;
                float v = src[yy * Ww + xx];
                acc0 += v * ws[(0 * 9 + c) * 9 + ky * 3 + kx];
                acc1 += v * ws[(1 * 9 + c) * 9 + ky * 3 + kx];
            }
        }
    }
    g_h[((size_t)(n * 2 + 0) * Hh + i) * Ww + j] = acc0;
    g_h[((size_t)(n * 2 + 1) * Hh + i) * Ww + j] = acc1;
}

// ---- kernel 2: fused dilated conv_off + sigmoid + DCN + 1x1 conv + relu + 2x2 maxpool ----
// thread handles a 2x2 output block -> writes pooled value directly (transposed layout)
__global__ __launch_bounds__(128) void dcn_kernel(
    const float* __restrict__ w_off,
    const float* __restrict__ w_dcn, const float* __restrict__ b_dcn,
    const float* __restrict__ w2, const float* __restrict__ b2)
{
    __shared__ float wofs[486];
    __shared__ float wds[36];
    __shared__ float bds[2], w2s[4], b2s[2];
    int tid = threadIdx.x;
    for (int t = tid; t < 486; t += 128) wofs[t] = w_off[t];
    if (tid < 36) wds[tid] = w_dcn[tid];
    if (tid < 4)  w2s[tid] = w2[tid];
    if (tid < 2)  { bds[tid] = b_dcn[tid]; b2s[tid] = b2[tid]; }
    __syncthreads();

    int n  = blockIdx.y;
    int pi = blockIdx.x * 2 + (tid >> 6);   // pooled row 0..63
    int pj = tid & 63;                      // pooled col 0..63

    const float* hn0 = g_h + (size_t)(n * 2 + 0) * Hh * Ww;
    const float* hn1 = g_h + (size_t)(n * 2 + 1) * Hh * Ww;

    float mx0 = -INFINITY, mx1 = -INFINITY;

    #pragma unroll
    for (int di = 0; di < 2; ++di)
    #pragma unroll
    for (int dj = 0; dj < 2; ++dj) {
        int i = pi * 2 + di, j = pj * 2 + dj;

        // conv_off: 27 channels, dilation 3, pad 3, no bias
        float om[27];
        #pragma unroll
        for (int m = 0; m < 27; ++m) om[m] = 0.f;
        #pragma unroll
        for (int ky = 0; ky < 3; ++ky) {
            int yy = i + (ky - 1) * 3;
            if (yy < 0 || yy >= Hh) continue;
            #pragma unroll
            for (int kx = 0; kx < 3; ++kx) {
                int xx = j + (kx - 1) * 3;
                if (xx < 0 || xx >= Ww) continue;
                float v0 = hn0[yy * Ww + xx];
                float v1 = hn1[yy * Ww + xx];
                const float* wp = wofs + ky * 3 + kx;   // [(m*2+c)*9 + tap]
                #pragma unroll
                for (int m = 0; m < 27; ++m)
                    om[m] += v0 * wp[m * 18] + v1 * wp[m * 18 + 9];
            }
        }

        // modulated deformable conv
        float out0 = bds[0], out1 = bds[1];
        #pragma unroll
        for (int k = 0; k < 9; ++k) {
            float dyv = om[2 * k];
            float dxv = om[2 * k + 1];
            float mmv = 1.f / (1.f + expf(-om[18 + k]));
            float py = dyv + (float)((k / 3 - 1) * 3 + i);
            float px = dxv + (float)((k % 3 - 1) * 3 + j);
            float y0f = floorf(py), x0f = floorf(px);
            int y0 = (int)y0f, x0 = (int)x0f;
            float ly = py - y0f, lx = px - x0f;
            float w00 = (1.f - ly) * (1.f - lx);
            float w01 = (1.f - ly) * lx;
            float w10 = ly * (1.f - lx);
            float w11 = ly * lx;
            float s0 = 0.f, s1 = 0.f;
            bool yv0 = (y0 >= 0) && (y0 < Hh);
            bool yv1 = (y0 + 1 >= 0) && (y0 + 1 < Hh);
            bool xv0 = (x0 >= 0) && (x0 < Ww);
            bool xv1 = (x0 + 1 >= 0) && (x0 + 1 < Ww);
            if (yv0) {
                int rb = y0 * Ww;
                if (xv0) { float a = hn0[rb + x0];     float b = hn1[rb + x0];     s0 += a * w00; s1 += b * w00; }
                if (xv1) { float a = hn0[rb + x0 + 1]; float b = hn1[rb + x0 + 1]; s0 += a * w01; s1 += b * w01; }
            }
            if (yv1) {
                int rb = (y0 + 1) * Ww;
                if (xv0) { float a = hn0[rb + x0];     float b = hn1[rb + x0];     s0 += a * w10; s1 += b * w10; }
                if (xv1) { float a = hn0[rb + x0 + 1]; float b = hn1[rb + x0 + 1]; s0 += a * w11; s1 += b * w11; }
            }
            s0 *= mmv; s1 *= mmv;
            // w_dcn[o][c][k] at wds[o*18 + c*9 + k]
            out0 += s0 * wds[k]      + s1 * wds[9 + k];
            out1 += s0 * wds[18 + k] + s1 * wds[27 + k];
        }

        // 1x1 conv + relu
        float r0 = fmaxf(out0 * w2s[0] + out1 * w2s[1] + b2s[0], 0.f);
        float r1 = fmaxf(out0 * w2s[2] + out1 * w2s[3] + b2s[1], 0.f);
        mx0 = fmaxf(mx0, r0);
        mx1 = fmaxf(mx1, r1);
    }

    int pk = pi * 64 + pj;                        // per-channel pooled index
    g_actT[(size_t)(0    + pk) * Nn + n] = mx0;   // channel 0
    g_actT[(size_t)(4096 + pk) * Nn + n] = mx1;   // channel 1
}

// ---------------- FC GEMM: OutT[o][n] = act(W[o][:]·A[:][n] + b[o]) ----------------
template<int K, int OT, int OPT, bool RELU>
__device__ __forceinline__ void fc_body(
    const float* __restrict__ W, const float* __restrict__ bias,
    const float* __restrict__ A, float* __restrict__ OutT)
{
    __shared__ __align__(16) float As[32 * 128];
    __shared__ __align__(16) float Wsm[32 * OT];
    int tid = threadIdx.x;
    int o0 = blockIdx.x * OT;
    int og = tid >> 6;          // 0..3
    int ng = tid & 63;          // 0..63
    int ob = og * OPT;
    int n0 = ng * 2;

    float acc[OPT][2];
    #pragma unroll
    for (int p = 0; p < OPT; ++p) { acc[p][0] = 0.f; acc[p][1] = 0.f; }

    for (int k0 = 0; k0 < K; k0 += 32) {
        const float4* Ag = (const float4*)(A + (size_t)k0 * 128);
        float4* As4 = (float4*)As;
        for (int t = tid; t < 1024; t += 256) As4[t] = Ag[t];
        for (int t = tid; t < OT * 32; t += 256) {
            int oo = t >> 5, kk = t & 31;
            Wsm[kk * OT + oo] = W[(size_t)(o0 + oo) * K + k0 + kk];
        }
        __syncthreads();
        #pragma unroll
        for (int kk = 0; kk < 32; ++kk) {
            float2 a = *(const float2*)(As + kk * 128 + n0);
            if (OPT == 4) {
                float4 w = *(const float4*)(Wsm + kk * OT + ob);
                acc[0][0] += a.x * w.x; acc[0][1] += a.y * w.x;
                acc[1][0] += a.x * w.y; acc[1][1] += a.y * w.y;
                acc[2][0] += a.x * w.z; acc[2][1] += a.y * w.z;
                acc[3][0] += a.x * w.w; acc[3][1] += a.y * w.w;
            } else {
                float2 w = *(const float2*)(Wsm + kk * OT + ob);
                acc[0][0] += a.x * w.x; acc[0][1] += a.y * w.x;
                acc[1][0] += a.x * w.y; acc[1][1] += a.y * w.y;
            }
        }
        __syncthreads();
    }

    #pragma unroll
    for (int p = 0; p < OPT; ++p) {
        int o = o0 + ob + p;
        float bv = bias[o];
        float v0 = acc[p][0] + bv;
        float v1 = acc[p][1] + bv;
        if (RELU) { v0 = fmaxf(v0, 0.f); v1 = fmaxf(v1, 0.f); }
        OutT[(size_t)o * 128 + n0]     = v0;
        OutT[(size_t)o * 128 + n0 + 1] = v1;
    }
}

__global__ __launch_bounds__(256) void fc1_kernel(const float* __restrict__ W,
                                                  const float* __restrict__ b)
{
    fc_body<8192, 16, 4, true>(W, b, g_actT, g_a1T);
}

__global__ __launch_bounds__(256) void fc2_kernel(const float* __restrict__ W,
                                                  const float* __restrict__ b)
{
    fc_body<2048, 8, 2, true>(W, b, g_a1T, g_a2T);
}

// ---------------- FC3 + sigmoid ----------------
__global__ __launch_bounds__(128) void fc3_kernel(const float* __restrict__ io_w,
                                                  const float* __restrict__ io_b,
                                                  float* __restrict__ out)
{
    int n = threadIdx.x;
    float acc = 0.f;
    #pragma unroll 4
    for (int k = 0; k < 1024; ++k)
        acc += g_a2T[(size_t)k * 128 + n] * io_w[k];
    acc += io_b[0];
    out[n] = 1.f / (1.f + expf(-acc));
}

// ---------------- launch ----------------
extern "C" void kernel_launch(void* const* d_in, const int* in_sizes, int n_in,
                              void* d_out, int out_size)
{
    const float* mask  = (const float*)d_in[0];
    const float* x     = (const float*)d_in[1];
    const float* w1    = (const float*)d_in[2];
    const float* b1    = (const float*)d_in[3];
    const float* w_off = (const float*)d_in[4];
    const float* w_dcn = (const float*)d_in[5];
    const float* b_dcn = (const float*)d_in[6];
    const float* w2    = (const float*)d_in[7];
    const float* b2    = (const float*)d_in[8];
    const float* fc1_w = (const float*)d_in[9];
    const float* fc1_b = (const float*)d_in[10];
    const float* fc2_w = (const float*)d_in[11];
    const float* fc2_b = (const float*)d_in[12];
    const float* io_w  = (const float*)d_in[13];
    const float* io_b  = (const float*)d_in[14];
    float* out = (float*)d_out;

    dim3 g1(Hh, Nn);
    conv1_kernel<<<g1, 128>>>(x, mask, w1, b1);

    dim3 g2(32, Nn);   // 32 row-pairs * (2 rows via tid>>6), 64 cols
    dcn_kernel<<<g2, 128>>>(w_off, w_dcn, b_dcn, w2, b2);

    fc1_kernel<<<2048 / 16, 256>>>(fc1_w, fc1_b);
    fc2_kernel<<<1024 / 8, 256>>>(fc2_w, fc2_b);
    fc3_kernel<<<1, 128>>>(io_w, io_b, out);
}

// round 6
// speedup vs baseline: 2.5125x; 2.5125x over previous
#include <cuda_runtime.h>
#include <math.h>

#define Nn 128
#define Hh 128
#define Ww 128
typedef unsigned long long ull;

// ---------------- device scratch (allocation-free) ----------------
__device__ __align__(16) float2 g_h2[Nn * Hh * Ww];   // conv1 out, channel-interleaved [n][y][x] -> (c0,c1)
__device__ __align__(16) float  g_actT[8192 * Nn];    // pooled activation, [k][n]
__device__ __align__(16) float  g_a1T[2048 * Nn];     // fc1 out, [o][n]
__device__ __align__(16) float  g_a2T[1024 * Nn];     // fc2 out, [o][n]

// ---------------- f32x2 helpers (FFMA2: 2x fp32 throughput) ----------------
__device__ __forceinline__ ull pack2(float lo, float hi) {
    ull r; asm("mov.b64 %0, {%1, %2};" : "=l"(r) : "f"(lo), "f"(hi)); return r;
}
__device__ __forceinline__ ull pack2dup(float v) {
    ull r; asm("mov.b64 %0, {%1, %1};" : "=l"(r) : "f"(v)); return r;
}
__device__ __forceinline__ void unpack2(ull v, float& a, float& b) {
    asm("mov.b64 {%0, %1}, %2;" : "=f"(a), "=f"(b) : "l"(v));
}
__device__ __forceinline__ ull fma2(ull a, ull b, ull c) {
    ull d; asm("fma.rn.f32x2 %0, %1, %2, %3;" : "=l"(d) : "l"(a), "l"(b), "l"(c)); return d;
}
__device__ __forceinline__ ull mul2(ull a, ull b) {
    ull d; asm("mul.rn.f32x2 %0, %1, %2;" : "=l"(d) : "l"(a), "l"(b)); return d;
}

// ---------------- cp.async helpers ----------------
__device__ __forceinline__ void cpa16(void* smem, const void* gmem) {
    unsigned s = (unsigned)__cvta_generic_to_shared(smem);
    asm volatile("cp.async.cg.shared.global [%0], [%1], 16;" :: "r"(s), "l"(gmem));
}
__device__ __forceinline__ void cpa_commit() { asm volatile("cp.async.commit_group;"); }
__device__ __forceinline__ void cpa_wait1()  { asm volatile("cp.async.wait_group 1;"); }
__device__ __forceinline__ void cpa_wait0()  { asm volatile("cp.async.wait_group 0;"); }

// ---------------- kernel 1: conv3x3 (9ch -> 2ch), pad 1, f32x2 over out-channels ----------------
__global__ __launch_bounds__(128) void conv1_kernel(
    const float* __restrict__ x, const float* __restrict__ mask,
    const float* __restrict__ w1, const float* __restrict__ b1)
{
    __shared__ ull ws2[81];
    int tid = threadIdx.x;
    if (tid < 81) ws2[tid] = pack2(w1[tid], w1[81 + tid]);   // (o0, o1) per (c,tap)
    __syncthreads();

    int j = tid, i = blockIdx.x, n = blockIdx.y;
    ull acc = pack2(b1[0], b1[1]);

    #pragma unroll
    for (int c = 0; c < 9; ++c) {
        const float* src = (c < 8) ? (x + (size_t)(n * 8 + c) * Hh * Ww)
                                   : (mask + (size_t)n * Hh * Ww);
        #pragma unroll
        for (int ky = 0; ky < 3; ++ky) {
            int yy = i + ky - 1;
            if (yy < 0 || yy >= Hh) continue;
            #pragma unroll
            for (int kx = 0; kx < 3; ++kx) {
                int xx = j + kx - 1;
                if (xx < 0 || xx >= Ww) continue;
                acc = fma2(pack2dup(src[yy * Ww + xx]), ws2[c * 9 + ky * 3 + kx], acc);
            }
        }
    }
    float a0, a1; unpack2(acc, a0, a1);
    g_h2[((size_t)n * Hh + i) * Ww + j] = make_float2(a0, a1);
}

// ---- kernel 2: fused dilated conv_off + sigmoid + DCN + 1x1 conv + relu + 2x2 maxpool ----
__global__ __launch_bounds__(128) void dcn_kernel(
    const float* __restrict__ w_off,
    const float* __restrict__ w_dcn, const float* __restrict__ b_dcn,
    const float* __restrict__ w2, const float* __restrict__ b2)
{
    __shared__ ull wof2[9 * 27];     // [tap][m] -> (w_off[m][0][tap], w_off[m][1][tap])
    __shared__ ull wdA[9], wdB[9];   // (w_dcn[o][0][k], w_dcn[o][1][k])
    __shared__ float bds[2], w2s[4], b2s[2];
    int tid = threadIdx.x;
    for (int t = tid; t < 243; t += 128) {
        int tap = t / 27, m = t % 27;
        wof2[t] = pack2(w_off[m * 18 + tap], w_off[m * 18 + 9 + tap]);
    }
    if (tid < 9) {
        wdA[tid] = pack2(w_dcn[tid],      w_dcn[9 + tid]);
        wdB[tid] = pack2(w_dcn[18 + tid], w_dcn[27 + tid]);
    }
    if (tid < 4) w2s[tid] = w2[tid];
    if (tid < 2) { bds[tid] = b_dcn[tid]; b2s[tid] = b2[tid]; }
    __syncthreads();

    int n  = blockIdx.y;
    int pi = blockIdx.x * 2 + (tid >> 6);
    int pj = tid & 63;

    const float2* hp = g_h2 + (size_t)n * Hh * Ww;
    const ull* hpu = (const ull*)hp;

    float mx0 = -INFINITY, mx1 = -INFINITY;

    #pragma unroll
    for (int di = 0; di < 2; ++di)
    #pragma unroll
    for (int dj = 0; dj < 2; ++dj) {
        int i = pi * 2 + di, j = pj * 2 + dj;

        // conv_off: dilation 3, pad 3; channel-pair packed in f32x2
        ull om2[27];
        #pragma unroll
        for (int m = 0; m < 27; ++m) om2[m] = 0ULL;
        #pragma unroll
        for (int ky = 0; ky < 3; ++ky) {
            int yy = i + (ky - 1) * 3;
            if (yy < 0 || yy >= Hh) continue;
            #pragma unroll
            for (int kx = 0; kx < 3; ++kx) {
                int xx = j + (kx - 1) * 3;
                if (xx < 0 || xx >= Ww) continue;
                ull v2 = hpu[yy * Ww + xx];
                const ull* wp = &wof2[(ky * 3 + kx) * 27];
                #pragma unroll
                for (int m = 0; m < 27; ++m) om2[m] = fma2(v2, wp[m], om2[m]);
            }
        }
        float om[27];
        #pragma unroll
        for (int m = 0; m < 27; ++m) { float a, b; unpack2(om2[m], a, b); om[m] = a + b; }

        // modulated deformable conv (both channels packed)
        ull outA = 0ULL, outB = 0ULL;
        #pragma unroll
        for (int k = 0; k < 9; ++k) {
            float dyv = om[2 * k];
            float dxv = om[2 * k + 1];
            float mmv = 1.f / (1.f + __expf(-om[18 + k]));
            float py = dyv + (float)((k / 3 - 1) * 3 + i);
            float px = dxv + (float)((k % 3 - 1) * 3 + j);
            float y0f = floorf(py), x0f = floorf(px);
            int y0 = (int)y0f, x0 = (int)x0f;
            float ly = py - y0f, lx = px - x0f;
            float w00 = (1.f - ly) * (1.f - lx);
            float w01 = (1.f - ly) * lx;
            float w10 = ly * (1.f - lx);
            float w11 = ly * lx;
            ull s2 = 0ULL;
            bool xv0 = (x0 >= 0) && (x0 < Ww);
            bool xv1 = (x0 + 1 >= 0) && (x0 + 1 < Ww);
            if (y0 >= 0 && y0 < Hh) {
                const ull* row = hpu + y0 * Ww;
                if (xv0) s2 = fma2(row[x0],     pack2dup(w00), s2);
                if (xv1) s2 = fma2(row[x0 + 1], pack2dup(w01), s2);
            }
            if (y0 + 1 >= 0 && y0 + 1 < Hh) {
                const ull* row = hpu + (y0 + 1) * Ww;
                if (xv0) s2 = fma2(row[x0],     pack2dup(w10), s2);
                if (xv1) s2 = fma2(row[x0 + 1], pack2dup(w11), s2);
            }
            s2 = mul2(s2, pack2dup(mmv));
            outA = fma2(s2, wdA[k], outA);
            outB = fma2(s2, wdB[k], outB);
        }
        float a0, a1, c0, c1;
        unpack2(outA, a0, a1); unpack2(outB, c0, c1);
        float out0 = bds[0] + a0 + a1;
        float out1 = bds[1] + c0 + c1;

        float r0 = fmaxf(out0 * w2s[0] + out1 * w2s[1] + b2s[0], 0.f);
        float r1 = fmaxf(out0 * w2s[2] + out1 * w2s[3] + b2s[1], 0.f);
        mx0 = fmaxf(mx0, r0);
        mx1 = fmaxf(mx1, r1);
    }

    int pk = pi * 64 + pj;
    g_actT[(size_t)(0    + pk) * Nn + n] = mx0;
    g_actT[(size_t)(4096 + pk) * Nn + n] = mx1;
}

// ---------------- FC GEMM with cp.async double buffering + FFMA2 ----------------
// OutT[o][n] = act(W[o][:]·A[:][n] + b[o]); A is [K][128]
template<int K, int OT, int OPT, bool RELU>
__device__ __forceinline__ void fc_body2(
    const float* __restrict__ W, const float* __restrict__ bias,
    const float* __restrict__ A, float* __restrict__ OutT)
{
    __shared__ __align__(16) float As[2][32 * 128];
    __shared__ __align__(16) float Ws[2][OT * 32];

    int tid = threadIdx.x;
    int o0 = blockIdx.x * OT;
    int og = tid >> 6;           // 0..3
    int ng = tid & 63;           // 0..63
    int ob = og * OPT;
    int n0 = ng * 2;

    ull acc2[OPT];
    #pragma unroll
    for (int p = 0; p < OPT; ++p) acc2[p] = 0ULL;

    const int NCH = K / 32;

    // --- chunk loader ---
    auto load_chunk = [&](int c, int buf) {
        const float* Ag = A + (size_t)c * 32 * 128;
        #pragma unroll
        for (int r = 0; r < 4; ++r) {
            int t = tid + r * 256;                // 1024 x 16B
            cpa16(&As[buf][t * 4], Ag + t * 4);
        }
        if (tid < OT * 8) {
            int oo = tid >> 3, seg = tid & 7;
            cpa16(&Ws[buf][oo * 32 + seg * 4],
                  W + (size_t)(o0 + oo) * K + c * 32 + seg * 4);
        }
    };

    load_chunk(0, 0);
    cpa_commit();

    for (int c = 0; c < NCH; ++c) {
        int buf = c & 1;
        if (c + 1 < NCH) {
            load_chunk(c + 1, buf ^ 1);
            cpa_commit();
            cpa_wait1();
        } else {
            cpa_wait0();
        }
        __syncthreads();

        const float* Ab = As[buf];
        const float* Wb = Ws[buf];
        #pragma unroll
        for (int kk = 0; kk < 32; ++kk) {
            ull a2 = *(const ull*)(Ab + kk * 128 + n0);
            #pragma unroll
            for (int p = 0; p < OPT; ++p)
                acc2[p] = fma2(pack2dup(Wb[(ob + p) * 32 + kk]), a2, acc2[p]);
        }
        __syncthreads();
    }

    #pragma unroll
    for (int p = 0; p < OPT; ++p) {
        int o = o0 + ob + p;
        float bv = bias[o];
        float v0, v1; unpack2(acc2[p], v0, v1);
        v0 += bv; v1 += bv;
        if (RELU) { v0 = fmaxf(v0, 0.f); v1 = fmaxf(v1, 0.f); }
        OutT[(size_t)o * 128 + n0]     = v0;
        OutT[(size_t)o * 128 + n0 + 1] = v1;
    }
}

__global__ __launch_bounds__(256) void fc1_kernel(const float* __restrict__ W,
                                                  const float* __restrict__ b)
{
    fc_body2<8192, 16, 4, true>(W, b, g_actT, g_a1T);
}

__global__ __launch_bounds__(256) void fc2_kernel(const float* __restrict__ W,
                                                  const float* __restrict__ b)
{
    fc_body2<2048, 8, 2, true>(W, b, g_a1T, g_a2T);
}

// ---------------- FC3 + sigmoid: one block per n ----------------
__global__ __launch_bounds__(256) void fc3_kernel(const float* __restrict__ io_w,
                                                  const float* __restrict__ io_b,
                                                  float* __restrict__ out)
{
    __shared__ float red[256];
    int n = blockIdx.x, tid = threadIdx.x;
    float acc = 0.f;
    #pragma unroll 4
    for (int k = tid; k < 1024; k += 256)
        acc += g_a2T[(size_t)k * 128 + n] * io_w[k];
    red[tid] = acc;
    __syncthreads();
    #pragma unroll
    for (int s = 128; s > 0; s >>= 1) {
        if (tid < s) red[tid] += red[tid + s];
        __syncthreads();
    }
    if (tid == 0) out[n] = 1.f / (1.f + __expf(-(red[0] + io_b[0])));
}

// ---------------- launch ----------------
extern "C" void kernel_launch(void* const* d_in, const int* in_sizes, int n_in,
                              void* d_out, int out_size)
{
    const float* mask  = (const float*)d_in[0];
    const float* x     = (const float*)d_in[1];
    const float* w1    = (const float*)d_in[2];
    const float* b1    = (const float*)d_in[3];
    const float* w_off = (const float*)d_in[4];
    const float* w_dcn = (const float*)d_in[5];
    const float* b_dcn = (const float*)d_in[6];
    const float* w2    = (const float*)d_in[7];
    const float* b2    = (const float*)d_in[8];
    const float* fc1_w = (const float*)d_in[9];
    const float* fc1_b = (const float*)d_in[10];
    const float* fc2_w = (const float*)d_in[11];
    const float* fc2_b = (const float*)d_in[12];
    const float* io_w  = (const float*)d_in[13];
    const float* io_b  = (const float*)d_in[14];
    float* out = (float*)d_out;

    dim3 g1(Hh, Nn);
    conv1_kernel<<<g1, 128>>>(x, mask, w1, b1);

    dim3 g2(32, Nn);
    dcn_kernel<<<g2, 128>>>(w_off, w_dcn, b_dcn, w2, b2);

    fc1_kernel<<<2048 / 16, 256>>>(fc1_w, fc1_b);
    fc2_kernel<<<1024 / 8, 256>>>(fc2_w, fc2_b);
    fc3_kernel<<<128, 256>>>(io_w, io_b, out);
}